// round 14
// baseline (speedup 1.0000x reference)
#include <cuda_runtime.h>
#include <cuda_bf16.h>
#include <cstdint>

// Problem constants
#define BPC   4
#define NW    4
#define NP    16
#define NN    1024
#define DD    32
#define NFEAT (NN*DD)
#define FSZ   (NP*NFEAT)

// Feature buffer indices
#define IX   0
#define IY1  1
#define IY2  2
#define IY4  3
#define IY8  4
#define ITA  5
#define ITB  6
#define IF0  7
#define IF1  8
#define IF2  9
#define IA1  10
#define IA2  11
#define IA3  12
#define IA4  13
#define IA5  14
#define IA6  15
#define IA7  16
#define IA8  17
#define IB1  18
#define IB2  19
#define IB3  20
#define IB4  21
#define IB5  22
#define IB6  23
#define IB7  24
#define IB8  25
#define IS01 26
#define IS02 27
#define IS12 28
#define NBUF 29

__device__ __nv_bfloat16 g_Whi[(size_t)NP * NN * NN];  // 32 MB
__device__ __nv_bfloat16 g_Wlo[(size_t)NP * NN * NN];  // 32 MB
__device__ float g_feat[NBUF][FSZ];                    // fp32 (epilogue/pool)
// split bf16 features in [n][k] layout: index p*NFEAT + n*NN + k
__device__ __nv_bfloat16 g_fH[NBUF][FSZ];
__device__ __nv_bfloat16 g_fL[NBUF][FSZ];
__device__ float g_sq[NP * NN];
__device__ float g_invdeg[NP * NN];

__constant__ int c_pool_idx[7] = { IX, IF0, IF1, IF2, IS01, IS02, IS12 };

// ---------------------------------------------------------------------------
// helpers
// ---------------------------------------------------------------------------
__device__ __forceinline__ uint32_t smem_u32(const void* p) {
    uint32_t a;
    asm("{ .reg .u64 t; cvta.to.shared.u64 t, %1; cvt.u32.u64 %0, t; }"
        : "=r"(a) : "l"(p));
    return a;
}
#define CVT_BF16X2(res, a, b) \
    asm("cvt.rn.bf16x2.f32 %0, %1, %2;" : "=r"(res) : "f"(b), "f"(a))

__device__ __forceinline__ void cp16(uint32_t s, const void* g) {
    asm volatile("cp.async.cg.shared.global [%0], [%1], 16;" :: "r"(s), "l"(g));
}
#define CP_COMMIT() asm volatile("cp.async.commit_group;" ::: "memory")
#define CP_WAIT0()  asm volatile("cp.async.wait_group 0;" ::: "memory")

__device__ __forceinline__ void ldsm4(uint32_t* r, uint32_t a) {
    asm volatile("ldmatrix.sync.aligned.m8n8.x4.shared.b16 {%0,%1,%2,%3}, [%4];"
                 : "=r"(r[0]), "=r"(r[1]), "=r"(r[2]), "=r"(r[3]) : "r"(a));
}
__device__ __forceinline__ void ldsm2(uint32_t* r, uint32_t a) {
    asm volatile("ldmatrix.sync.aligned.m8n8.x2.shared.b16 {%0,%1}, [%2];"
                 : "=r"(r[0]), "=r"(r[1]) : "r"(a));
}
__device__ __forceinline__ void mma16816(float* d, const uint32_t* a, const uint32_t* b) {
    asm volatile(
        "mma.sync.aligned.m16n8k16.row.col.f32.bf16.bf16.f32 "
        "{%0,%1,%2,%3}, {%4,%5,%6,%7}, {%8,%9}, {%0,%1,%2,%3};"
        : "+f"(d[0]), "+f"(d[1]), "+f"(d[2]), "+f"(d[3])
        : "r"(a[0]), "r"(a[1]), "r"(a[2]), "r"(a[3]), "r"(b[0]), "r"(b[1]));
}

// exp(t) for t in [-0.694, ~0]: degree-6 Taylor, abs err <= 1.6e-5
__device__ __forceinline__ float exp_poly(float t) {
    float p = fmaf(t, 1.0f / 720.0f, 1.0f / 120.0f);
    p = fmaf(t, p, 1.0f / 24.0f);
    p = fmaf(t, p, 1.0f / 6.0f);
    p = fmaf(t, p, 0.5f);
    p = fmaf(t, p, 1.0f);
    p = fmaf(t, p, 1.0f);
    return p;
}

__device__ __forceinline__ void split_bf16(float v, __nv_bfloat16& h, __nv_bfloat16& l) {
    h = __float2bfloat16_rn(v);
    l = __float2bfloat16_rn(v - __bfloat162float(h));
}

// ---------------------------------------------------------------------------
// X fp32 (natural layout) : X[p][n][d] = pc[b][n][d] * alphas[w][d]
// ---------------------------------------------------------------------------
__global__ void build_X_kernel(const float* __restrict__ pc,
                               const float* __restrict__ alphas) {
    int idx = blockIdx.x * blockDim.x + threadIdx.x;
    int d = idx & 31;
    int n = (idx >> 5) & 1023;
    int p = idx >> 15;
    int b = p >> 2;
    int w = p & 3;
    g_feat[IX][idx] = pc[(b * NN + n) * DD + d] * alphas[w * DD + d];
}

// X split bf16 in [d][n] (=[n-of-B][k]) layout
__global__ void build_Xsplit_kernel(const float* __restrict__ pc,
                                    const float* __restrict__ alphas) {
    int idx = blockIdx.x * blockDim.x + threadIdx.x;   // (p, d, n)
    int n = idx & 1023;
    int d = (idx >> 10) & 31;
    int p = idx >> 15;
    int b = p >> 2;
    int w = p & 3;
    float x = pc[(b * NN + n) * DD + d] * alphas[w * DD + d];
    __nv_bfloat16 h, l;
    split_bf16(x, h, l);
    g_fH[IX][p * NFEAT + d * NN + n] = h;
    g_fL[IX][p * NFEAT + d * NN + n] = l;
}

// ---------------------------------------------------------------------------
__global__ void sq_kernel() {
    int gr = blockIdx.x * blockDim.x + threadIdx.x;
    const float4* row = (const float4*)&g_feat[IX][(size_t)gr * DD];
    float s = 0.f;
#pragma unroll
    for (int i = 0; i < 8; i++) {
        float4 v = row[i];
        s += v.x * v.x + v.y * v.y + v.z * v.z + v.w * v.w;
    }
    g_sq[gr] = s;
}

// ---------------------------------------------------------------------------
// W[p][i][j] = K if K >= 0.5 else 0 ; emit bf16 split hi/lo directly.
// ---------------------------------------------------------------------------
__global__ __launch_bounds__(256) void w_kernel(const float* __restrict__ sigma_ptr) {
    __shared__ float Xis[DD][68];
    __shared__ float Xjs[DD][68];

    int p  = blockIdx.z;
    int i0 = blockIdx.y * 64;
    int j0 = blockIdx.x * 64;
    int tid = threadIdx.x;
    float sigma = sigma_ptr[0];
    float invsig = 1.0f / sigma;
    float thr = sigma * 0.69314718055994530942f;

    const float* Xp = &g_feat[IX][(size_t)p * NFEAT];

#pragma unroll
    for (int it = 0; it < 2; it++) {
        int fi = tid + it * 256;
        int r  = fi >> 3;
        int c4 = (fi & 7) << 2;
        float4 vi = *(const float4*)(Xp + (i0 + r) * DD + c4);
        Xis[c4 + 0][r] = vi.x; Xis[c4 + 1][r] = vi.y;
        Xis[c4 + 2][r] = vi.z; Xis[c4 + 3][r] = vi.w;
        float4 vj = *(const float4*)(Xp + (j0 + r) * DD + c4);
        Xjs[c4 + 0][r] = vj.x; Xjs[c4 + 1][r] = vj.y;
        Xjs[c4 + 2][r] = vj.z; Xjs[c4 + 3][r] = vj.w;
    }
    __syncthreads();

    int ti = tid >> 4;
    int tj = tid & 15;
    float acc[4][4];
#pragma unroll
    for (int a = 0; a < 4; a++)
#pragma unroll
        for (int b = 0; b < 4; b++) acc[a][b] = 0.f;

#pragma unroll
    for (int d = 0; d < DD; d++) {
        float4 xa = *(const float4*)&Xis[d][ti * 4];
        float4 xb = *(const float4*)&Xjs[d][tj * 4];
        float ar[4] = { xa.x, xa.y, xa.z, xa.w };
        float br[4] = { xb.x, xb.y, xb.z, xb.w };
#pragma unroll
        for (int a = 0; a < 4; a++)
#pragma unroll
            for (int b = 0; b < 4; b++) acc[a][b] += ar[a] * br[b];
    }

    float sqi[4], sqj[4];
#pragma unroll
    for (int a = 0; a < 4; a++) sqi[a] = g_sq[p * NN + i0 + ti * 4 + a];
#pragma unroll
    for (int b = 0; b < 4; b++) sqj[b] = g_sq[p * NN + j0 + tj * 4 + b];

#pragma unroll
    for (int a = 0; a < 4; a++) {
        float wvals[4];
#pragma unroll
        for (int b = 0; b < 4; b++) {
            float dist = sqi[a] + sqj[b] - 2.f * acc[a][b];
            float K = exp_poly(-dist * invsig);
            wvals[b] = (dist <= thr) ? K : 0.f;
        }
        uint32_t hp0, hp1, lp0, lp1;
        CVT_BF16X2(hp0, wvals[0], wvals[1]);
        CVT_BF16X2(hp1, wvals[2], wvals[3]);
        float h0 = __uint_as_float(hp0 << 16);
        float h1 = __uint_as_float(hp0 & 0xffff0000u);
        float h2 = __uint_as_float(hp1 << 16);
        float h3 = __uint_as_float(hp1 & 0xffff0000u);
        CVT_BF16X2(lp0, wvals[0] - h0, wvals[1] - h1);
        CVT_BF16X2(lp1, wvals[2] - h2, wvals[3] - h3);
        size_t off = (size_t)p * NN * NN + (size_t)(i0 + ti * 4 + a) * NN + j0 + tj * 4;
        *(uint2*)((char*)g_Whi + off * 2) = make_uint2(hp0, hp1);
        *(uint2*)((char*)g_Wlo + off * 2) = make_uint2(lp0, lp1);
    }
}

// ---------------------------------------------------------------------------
__global__ void deg_kernel() {
    int gr = blockIdx.x * 8 + (threadIdx.x >> 5);
    int lane = threadIdx.x & 31;
    const uint32_t* H2 = (const uint32_t*)(g_Whi + (size_t)gr * NN);
    const uint32_t* L2 = (const uint32_t*)(g_Wlo + (size_t)gr * NN);
    float s = 0.f;
    for (int k = lane; k < 512; k += 32) {
        uint32_t h = H2[k], l = L2[k];
        s += __uint_as_float(h << 16) + __uint_as_float(h & 0xffff0000u);
        s += __uint_as_float(l << 16) + __uint_as_float(l & 0xffff0000u);
    }
#pragma unroll
    for (int o = 16; o > 0; o >>= 1) s += __shfl_down_sync(0xffffffffu, s, o);
    if (lane == 0) g_invdeg[gr] = 1.0f / s;
}

// ---------------------------------------------------------------------------
// Tensor-core apply; A and B both staged via cp.async (B pre-split in gmem).
// CTA: 64 rows x 32 cols x K=1024, 128 threads, grid 16 x NP (2 CTAs/SM).
// Epilogue writes fp32 out + split bf16 [n][k] via smem-bounce transpose.
// ---------------------------------------------------------------------------
#define A_SPL   5120                 // 64 rows * 80 B
#define A_TOT   10240                // hi + lo
#define B_SPL   2560                 // 32 n-rows * 80 B
#define B_JOB   5120                 // hi + lo
#define AOFF(b, sp) ((b) * A_TOT + (sp) * A_SPL)
#define BOFF(b, j, NJ) (2 * A_TOT + (b) * ((NJ) * B_JOB) + (j) * B_JOB)
// epilogue bounce (reuses the same smem after mainloop)
#define EP_PITCH 144                 // bytes per n-row (64 k * 2B + 16 pad)
#define EP_OH 0
#define EP_OL 4608
#define EP_AH 9216
#define EP_AL 13824

template <int NJ>
__global__ __launch_bounds__(128) void apply_kernel(int4 j0, int4 j1, int4 j2) {
    extern __shared__ __align__(16) char dsm[];
    uint32_t smb = smem_u32(dsm);

    int tid  = threadIdx.x;
    int lane = tid & 31;
    int wid  = tid >> 5;
    int p    = blockIdx.z;
    int row0 = blockIdx.x * 64;
    int4 jobs[3] = { j0, j1, j2 };

    const float* In[NJ];
    float*       Out[NJ];
    const __nv_bfloat16* FH[NJ];
    const __nv_bfloat16* FL[NJ];
#pragma unroll
    for (int j = 0; j < NJ; j++) {
        In[j]  = &g_feat[jobs[j].x][(size_t)p * NFEAT];
        Out[j] = &g_feat[jobs[j].y][(size_t)p * NFEAT];
        FH[j]  = &g_fH[jobs[j].x][(size_t)p * NFEAT];
        FL[j]  = &g_fL[jobs[j].x][(size_t)p * NFEAT];
    }
    const __nv_bfloat16* WhiP = g_Whi + ((size_t)(p * NN + row0)) * NN;
    const __nv_bfloat16* WloP = g_Wlo + ((size_t)(p * NN + row0)) * NN;

    float acc[NJ][4][4];
#pragma unroll
    for (int j = 0; j < NJ; j++)
#pragma unroll
        for (int n = 0; n < 4; n++)
#pragma unroll
            for (int q = 0; q < 4; q++) acc[j][n][q] = 0.f;

    // A: 64 rows x 32 k bf16 per split; 2 cp16/thread/split
#define STAGE_A(buf, k0)                                                        \
    do {                                                                        \
        _Pragma("unroll")                                                       \
        for (int it = 0; it < 2; it++) {                                        \
            int fi = tid + it * 128;                                            \
            int r  = fi >> 2;                                                   \
            int sg = fi & 3;                                                    \
            cp16(smb + AOFF(buf, 0) + r * 80 + sg * 16,                         \
                 WhiP + (size_t)r * NN + (k0) + sg * 8);                        \
            cp16(smb + AOFF(buf, 1) + r * 80 + sg * 16,                         \
                 WloP + (size_t)r * NN + (k0) + sg * 8);                        \
        }                                                                       \
    } while (0)

    // B: 32 n-rows x 32 k bf16 per split per job; 1 cp16/thread/split/job
#define STAGE_B(buf, k0)                                                        \
    do {                                                                        \
        int n  = tid >> 2;                                                      \
        int sg = tid & 3;                                                       \
        _Pragma("unroll")                                                       \
        for (int j = 0; j < NJ; j++) {                                          \
            cp16(smb + BOFF(buf, j, NJ) + n * 80 + sg * 16,                     \
                 FH[j] + (size_t)n * NN + (k0) + sg * 8);                       \
            cp16(smb + BOFF(buf, j, NJ) + B_SPL + n * 80 + sg * 16,             \
                 FL[j] + (size_t)n * NN + (k0) + sg * 8);                       \
        }                                                                       \
    } while (0)

    // prologue
    STAGE_A(0, 0);
    STAGE_B(0, 0);
    CP_COMMIT();

    for (int c = 0; c < 32; c++) {
        int buf = c & 1;
        CP_WAIT0();
        __syncthreads();

        if (c < 31) {
            STAGE_A(buf ^ 1, (c + 1) * 32);
            STAGE_B(buf ^ 1, (c + 1) * 32);
            CP_COMMIT();
        }

#pragma unroll
        for (int k16 = 0; k16 < 2; k16++) {
            uint32_t ah[4], al[4];
            uint32_t arow = (uint32_t)(wid * 16 + (lane & 15));
            uint32_t aoff = arow * 80 + k16 * 32 + (lane >> 4) * 16;
            ldsm4(ah, smb + AOFF(buf, 0) + aoff);
            ldsm4(al, smb + AOFF(buf, 1) + aoff);
#pragma unroll
            for (int j = 0; j < NJ; j++) {
#pragma unroll
                for (int nt = 0; nt < 4; nt++) {
                    uint32_t boff = (uint32_t)((nt * 8 + (lane & 7)) * 80 +
                                               k16 * 32 + ((lane >> 3) & 1) * 16);
                    uint32_t bh[2], bl[2];
                    ldsm2(bh, smb + BOFF(buf, j, NJ) + boff);
                    ldsm2(bl, smb + BOFF(buf, j, NJ) + B_SPL + boff);
                    mma16816(acc[j][nt], ah, bh);
                    mma16816(acc[j][nt], ah, bl);
                    mma16816(acc[j][nt], al, bh);
                }
            }
        }
        // no trailing store; next iter's CP_WAIT0/sync fences the new buffers
        if (c == 31) __syncthreads();   // protect smem before epilogue bounce
    }

    // epilogue
    int g = lane >> 2, tig = lane & 3;
    int kl0 = wid * 16 + g;            // local k 0..63
    int kl1 = kl0 + 8;
    int r0 = row0 + kl0;
    int r1 = row0 + kl1;
    float idg0 = g_invdeg[p * NN + r0];
    float idg1 = g_invdeg[p * NN + r1];

#pragma unroll
    for (int j = 0; j < NJ; j++) {
        const float* F = In[j];
        float* O = Out[j];
        const float* Dif = (jobs[j].z >= 0) ? &g_feat[jobs[j].z][(size_t)p * NFEAT] : nullptr;
        float*       Abs = (jobs[j].w >= 0) ? &g_feat[jobs[j].w][(size_t)p * NFEAT] : nullptr;

#pragma unroll
        for (int nt = 0; nt < 4; nt++) {
            int col = nt * 8 + 2 * tig;
            float2 v0 = *(const float2*)(F + r0 * DD + col);
            float2 v1 = *(const float2*)(F + r1 * DD + col);
            float2 o0, o1;
            o0.x = 0.5f * fmaf(acc[j][nt][0], idg0, v0.x);
            o0.y = 0.5f * fmaf(acc[j][nt][1], idg0, v0.y);
            o1.x = 0.5f * fmaf(acc[j][nt][2], idg1, v1.x);
            o1.y = 0.5f * fmaf(acc[j][nt][3], idg1, v1.y);
            *(float2*)(O + r0 * DD + col) = o0;
            *(float2*)(O + r1 * DD + col) = o1;

            // split Out into bounce smem [n][k_local]
            __nv_bfloat16 h, l;
            __nv_bfloat16* SH = (__nv_bfloat16*)(dsm + EP_OH);
            __nv_bfloat16* SL = (__nv_bfloat16*)(dsm + EP_OL);
            split_bf16(o0.x, h, l); SH[col * 72 + kl0] = h; SL[col * 72 + kl0] = l;
            split_bf16(o0.y, h, l); SH[(col + 1) * 72 + kl0] = h; SL[(col + 1) * 72 + kl0] = l;
            split_bf16(o1.x, h, l); SH[col * 72 + kl1] = h; SL[col * 72 + kl1] = l;
            split_bf16(o1.y, h, l); SH[(col + 1) * 72 + kl1] = h; SL[(col + 1) * 72 + kl1] = l;

            if (Dif) {
                float2 d0 = *(const float2*)(Dif + r0 * DD + col);
                float2 d1 = *(const float2*)(Dif + r1 * DD + col);
                float2 a0, a1;
                a0.x = fabsf(d0.x - o0.x); a0.y = fabsf(d0.y - o0.y);
                a1.x = fabsf(d1.x - o1.x); a1.y = fabsf(d1.y - o1.y);
                *(float2*)(Abs + r0 * DD + col) = a0;
                *(float2*)(Abs + r1 * DD + col) = a1;
                __nv_bfloat16* TH = (__nv_bfloat16*)(dsm + EP_AH);
                __nv_bfloat16* TL = (__nv_bfloat16*)(dsm + EP_AL);
                split_bf16(a0.x, h, l); TH[col * 72 + kl0] = h; TL[col * 72 + kl0] = l;
                split_bf16(a0.y, h, l); TH[(col + 1) * 72 + kl0] = h; TL[(col + 1) * 72 + kl0] = l;
                split_bf16(a1.x, h, l); TH[col * 72 + kl1] = h; TL[col * 72 + kl1] = l;
                split_bf16(a1.y, h, l); TH[(col + 1) * 72 + kl1] = h; TL[(col + 1) * 72 + kl1] = l;
            }
        }
        __syncthreads();

        // coalesced copy-out of split tiles: [32 n][64 k] bf16 per split
        {
            int n = tid >> 2;
            int q = tid & 3;
            size_t gidx = (size_t)p * NFEAT + (size_t)n * NN + row0 + q * 16;
            __nv_bfloat16* dH = &g_fH[jobs[j].y][gidx];
            __nv_bfloat16* dL = &g_fL[jobs[j].y][gidx];
#pragma unroll
            for (int e = 0; e < 2; e++) {
                *(uint4*)((char*)dH + e * 16) =
                    *(const uint4*)(dsm + EP_OH + n * EP_PITCH + q * 32 + e * 16);
                *(uint4*)((char*)dL + e * 16) =
                    *(const uint4*)(dsm + EP_OL + n * EP_PITCH + q * 32 + e * 16);
            }
            if (jobs[j].w >= 0) {
                __nv_bfloat16* aH = &g_fH[jobs[j].w][gidx];
                __nv_bfloat16* aL = &g_fL[jobs[j].w][gidx];
#pragma unroll
                for (int e = 0; e < 2; e++) {
                    *(uint4*)((char*)aH + e * 16) =
                        *(const uint4*)(dsm + EP_AH + n * EP_PITCH + q * 32 + e * 16);
                    *(uint4*)((char*)aL + e * 16) =
                        *(const uint4*)(dsm + EP_AL + n * EP_PITCH + q * 32 + e * 16);
                }
            }
        }
        __syncthreads();
    }
}

// ---------------------------------------------------------------------------
__global__ void pool_kernel(float* __restrict__ out) {
    __shared__ float red[8][32];
    int blk = blockIdx.x;
    int p   = blockIdx.y;
    int col = threadIdx.x & 31;
    int grp = threadIdx.x >> 5;
    const float* src = &g_feat[c_pool_idx[blk]][(size_t)p * NFEAT];
    float s = 0.f;
    for (int i = 0; i < 128; i++)
        s += src[(grp * 128 + i) * DD + col];
    red[grp][col] = s;
    __syncthreads();
    if (grp == 0) {
        float t = 0.f;
#pragma unroll
        for (int g = 0; g < 8; g++) t += red[g][col];
        int b = p >> 2, w = p & 3;
        out[b * (NW * 224) + w * 224 + blk * 32 + col] = t * (1.0f / 1024.0f);
    }
}

// ---------------------------------------------------------------------------
extern "C" void kernel_launch(void* const* d_in, const int* in_sizes, int n_in,
                              void* d_out, int out_size) {
    const float* pc     = (const float*)d_in[0];
    const float* alphas = (const float*)d_in[1];
    const float* sigma  = (const float*)d_in[2];
    float* out = (float*)d_out;

    const int smem1 = 2 * A_TOT + 2 * 1 * B_JOB;   // 30720
    const int smem2 = 2 * A_TOT + 2 * 2 * B_JOB;   // 40960
    const int smem3 = 2 * A_TOT + 2 * 3 * B_JOB;   // 51200
    cudaFuncSetAttribute(apply_kernel<1>, cudaFuncAttributeMaxDynamicSharedMemorySize, smem1);
    cudaFuncSetAttribute(apply_kernel<2>, cudaFuncAttributeMaxDynamicSharedMemorySize, smem2);
    cudaFuncSetAttribute(apply_kernel<3>, cudaFuncAttributeMaxDynamicSharedMemorySize, smem3);

    build_X_kernel<<<FSZ / 256, 256>>>(pc, alphas);
    build_Xsplit_kernel<<<FSZ / 256, 256>>>(pc, alphas);
    sq_kernel<<<(NP * NN) / 256, 256>>>();
    w_kernel<<<dim3(16, 16, NP), 256>>>(sigma);
    deg_kernel<<<(NP * NN) / 8, 256>>>();

    int4 dummy = make_int4(IX, ITA, -1, -1);
    dim3 grid(16, 1, NP);   // 256 CTAs, 64 rows each -> 2 CTAs/SM
    auto run1 = [&](int4 a) { apply_kernel<1><<<grid, 128, smem1>>>(a, dummy, dummy); };
    auto run2 = [&](int4 a, int4 b) { apply_kernel<2><<<grid, 128, smem2>>>(a, b, dummy); };
    auto run3 = [&](int4 a, int4 b, int4 c) { apply_kernel<3><<<grid, 128, smem3>>>(a, b, c); };
    #define J4(i, o, df, ab) make_int4(i, o, df, ab)

    run1(J4(IX,  IY1, -1, -1));
    run1(J4(IY1, IY2, IY1, IF0));
    run2(J4(IY2, ITA, -1, -1), J4(IF0, IA1, -1, -1));
    run2(J4(ITA, IY4, IY2, IF1), J4(IA1, IA2, -1, -1));
    run3(J4(IY4, ITB, -1, -1), J4(IA2, IA3, -1, -1), J4(IF1, IB1, -1, -1));
    run3(J4(ITB, ITA, -1, -1), J4(IA3, IA4, IA2, IS01), J4(IB1, IB2, -1, -1));
    run3(J4(ITA, ITB, -1, -1), J4(IA4, IA5, -1, -1), J4(IB2, IB3, -1, -1));
    run3(J4(ITB, IY8, IY4, IF2), J4(IA5, IA6, -1, -1), J4(IB3, IB4, -1, -1));
    run2(J4(IA6, IA7, -1, -1), J4(IB4, IB5, -1, -1));
    run2(J4(IA7, IA8, IA4, IS02), J4(IB5, IB6, -1, -1));
    run1(J4(IB6, IB7, -1, -1));
    run1(J4(IB7, IB8, IB4, IS12));

    pool_kernel<<<dim3(7, NP), 256>>>(out);
}

// round 15
// speedup vs baseline: 1.0004x; 1.0004x over previous
#include <cuda_runtime.h>
#include <cuda_bf16.h>
#include <cstdint>

// Problem constants
#define BPC   4
#define NW    4
#define NP    16
#define NN    1024
#define DD    32
#define NFEAT (NN*DD)
#define FSZ   (NP*NFEAT)

// Feature buffer indices
#define IX   0
#define IY1  1
#define IY2  2
#define IY4  3
#define IY8  4
#define ITA  5
#define ITB  6
#define IF0  7
#define IF1  8
#define IF2  9
#define IA1  10
#define IA2  11
#define IA3  12
#define IA4  13
#define IA5  14
#define IA6  15
#define IA7  16
#define IA8  17
#define IB1  18
#define IB2  19
#define IB3  20
#define IB4  21
#define IB5  22
#define IB6  23
#define IB7  24
#define IB8  25
#define IS01 26
#define IS02 27
#define IS12 28
#define NBUF 29

__device__ __nv_bfloat16 g_Whi[(size_t)NP * NN * NN];  // 32 MB
__device__ __nv_bfloat16 g_Wlo[(size_t)NP * NN * NN];  // 32 MB
__device__ float g_feat[NBUF][FSZ];                    // fp32 (epilogue/pool)
// split bf16 features in [n][k] layout: index p*NFEAT + n*NN + k
__device__ __nv_bfloat16 g_fH[NBUF][FSZ];
__device__ __nv_bfloat16 g_fL[NBUF][FSZ];
__device__ float g_sq[NP * NN];
__device__ float g_invdeg[NP * NN];

__constant__ int c_pool_idx[7] = { IX, IF0, IF1, IF2, IS01, IS02, IS12 };

// ---------------------------------------------------------------------------
// helpers
// ---------------------------------------------------------------------------
__device__ __forceinline__ uint32_t smem_u32(const void* p) {
    uint32_t a;
    asm("{ .reg .u64 t; cvta.to.shared.u64 t, %1; cvt.u32.u64 %0, t; }"
        : "=r"(a) : "l"(p));
    return a;
}
#define CVT_BF16X2(res, a, b) \
    asm("cvt.rn.bf16x2.f32 %0, %1, %2;" : "=r"(res) : "f"(b), "f"(a))

__device__ __forceinline__ void cp16(uint32_t s, const void* g) {
    asm volatile("cp.async.cg.shared.global [%0], [%1], 16;" :: "r"(s), "l"(g));
}
#define CP_COMMIT() asm volatile("cp.async.commit_group;" ::: "memory")
#define CP_WAIT0()  asm volatile("cp.async.wait_group 0;" ::: "memory")

__device__ __forceinline__ void ldsm4(uint32_t* r, uint32_t a) {
    asm volatile("ldmatrix.sync.aligned.m8n8.x4.shared.b16 {%0,%1,%2,%3}, [%4];"
                 : "=r"(r[0]), "=r"(r[1]), "=r"(r[2]), "=r"(r[3]) : "r"(a));
}
__device__ __forceinline__ void ldsm2(uint32_t* r, uint32_t a) {
    asm volatile("ldmatrix.sync.aligned.m8n8.x2.shared.b16 {%0,%1}, [%2];"
                 : "=r"(r[0]), "=r"(r[1]) : "r"(a));
}
__device__ __forceinline__ void mma16816(float* d, const uint32_t* a, const uint32_t* b) {
    asm volatile(
        "mma.sync.aligned.m16n8k16.row.col.f32.bf16.bf16.f32 "
        "{%0,%1,%2,%3}, {%4,%5,%6,%7}, {%8,%9}, {%0,%1,%2,%3};"
        : "+f"(d[0]), "+f"(d[1]), "+f"(d[2]), "+f"(d[3])
        : "r"(a[0]), "r"(a[1]), "r"(a[2]), "r"(a[3]), "r"(b[0]), "r"(b[1]));
}

// exp(t) for t in [-0.694, ~0]: degree-6 Taylor, abs err <= 1.6e-5
__device__ __forceinline__ float exp_poly(float t) {
    float p = fmaf(t, 1.0f / 720.0f, 1.0f / 120.0f);
    p = fmaf(t, p, 1.0f / 24.0f);
    p = fmaf(t, p, 1.0f / 6.0f);
    p = fmaf(t, p, 0.5f);
    p = fmaf(t, p, 1.0f);
    p = fmaf(t, p, 1.0f);
    return p;
}

__device__ __forceinline__ void split_bf16(float v, __nv_bfloat16& h, __nv_bfloat16& l) {
    h = __float2bfloat16_rn(v);
    l = __float2bfloat16_rn(v - __bfloat162float(h));
}

// ---------------------------------------------------------------------------
// X fp32 (natural layout) : X[p][n][d] = pc[b][n][d] * alphas[w][d]
// ---------------------------------------------------------------------------
__global__ void build_X_kernel(const float* __restrict__ pc,
                               const float* __restrict__ alphas) {
    int idx = blockIdx.x * blockDim.x + threadIdx.x;
    int d = idx & 31;
    int n = (idx >> 5) & 1023;
    int p = idx >> 15;
    int b = p >> 2;
    int w = p & 3;
    g_feat[IX][idx] = pc[(b * NN + n) * DD + d] * alphas[w * DD + d];
}

// X split bf16 in [d][n] (=[n-of-B][k]) layout
__global__ void build_Xsplit_kernel(const float* __restrict__ pc,
                                    const float* __restrict__ alphas) {
    int idx = blockIdx.x * blockDim.x + threadIdx.x;   // (p, d, n)
    int n = idx & 1023;
    int d = (idx >> 10) & 31;
    int p = idx >> 15;
    int b = p >> 2;
    int w = p & 3;
    float x = pc[(b * NN + n) * DD + d] * alphas[w * DD + d];
    __nv_bfloat16 h, l;
    split_bf16(x, h, l);
    g_fH[IX][p * NFEAT + d * NN + n] = h;
    g_fL[IX][p * NFEAT + d * NN + n] = l;
}

// ---------------------------------------------------------------------------
__global__ void sq_kernel() {
    int gr = blockIdx.x * blockDim.x + threadIdx.x;
    const float4* row = (const float4*)&g_feat[IX][(size_t)gr * DD];
    float s = 0.f;
#pragma unroll
    for (int i = 0; i < 8; i++) {
        float4 v = row[i];
        s += v.x * v.x + v.y * v.y + v.z * v.z + v.w * v.w;
    }
    g_sq[gr] = s;
}

// ---------------------------------------------------------------------------
// W[p][i][j] = K if K >= 0.5 else 0 ; emit bf16 split hi/lo directly.
// ---------------------------------------------------------------------------
__global__ __launch_bounds__(256) void w_kernel(const float* __restrict__ sigma_ptr) {
    __shared__ float Xis[DD][68];
    __shared__ float Xjs[DD][68];

    int p  = blockIdx.z;
    int i0 = blockIdx.y * 64;
    int j0 = blockIdx.x * 64;
    int tid = threadIdx.x;
    float sigma = sigma_ptr[0];
    float invsig = 1.0f / sigma;
    float thr = sigma * 0.69314718055994530942f;

    const float* Xp = &g_feat[IX][(size_t)p * NFEAT];

#pragma unroll
    for (int it = 0; it < 2; it++) {
        int fi = tid + it * 256;
        int r  = fi >> 3;
        int c4 = (fi & 7) << 2;
        float4 vi = *(const float4*)(Xp + (i0 + r) * DD + c4);
        Xis[c4 + 0][r] = vi.x; Xis[c4 + 1][r] = vi.y;
        Xis[c4 + 2][r] = vi.z; Xis[c4 + 3][r] = vi.w;
        float4 vj = *(const float4*)(Xp + (j0 + r) * DD + c4);
        Xjs[c4 + 0][r] = vj.x; Xjs[c4 + 1][r] = vj.y;
        Xjs[c4 + 2][r] = vj.z; Xjs[c4 + 3][r] = vj.w;
    }
    __syncthreads();

    int ti = tid >> 4;
    int tj = tid & 15;
    float acc[4][4];
#pragma unroll
    for (int a = 0; a < 4; a++)
#pragma unroll
        for (int b = 0; b < 4; b++) acc[a][b] = 0.f;

#pragma unroll
    for (int d = 0; d < DD; d++) {
        float4 xa = *(const float4*)&Xis[d][ti * 4];
        float4 xb = *(const float4*)&Xjs[d][tj * 4];
        float ar[4] = { xa.x, xa.y, xa.z, xa.w };
        float br[4] = { xb.x, xb.y, xb.z, xb.w };
#pragma unroll
        for (int a = 0; a < 4; a++)
#pragma unroll
            for (int b = 0; b < 4; b++) acc[a][b] += ar[a] * br[b];
    }

    float sqi[4], sqj[4];
#pragma unroll
    for (int a = 0; a < 4; a++) sqi[a] = g_sq[p * NN + i0 + ti * 4 + a];
#pragma unroll
    for (int b = 0; b < 4; b++) sqj[b] = g_sq[p * NN + j0 + tj * 4 + b];

#pragma unroll
    for (int a = 0; a < 4; a++) {
        float wvals[4];
#pragma unroll
        for (int b = 0; b < 4; b++) {
            float dist = sqi[a] + sqj[b] - 2.f * acc[a][b];
            float K = exp_poly(-dist * invsig);
            wvals[b] = (dist <= thr) ? K : 0.f;
        }
        uint32_t hp0, hp1, lp0, lp1;
        CVT_BF16X2(hp0, wvals[0], wvals[1]);
        CVT_BF16X2(hp1, wvals[2], wvals[3]);
        float h0 = __uint_as_float(hp0 << 16);
        float h1 = __uint_as_float(hp0 & 0xffff0000u);
        float h2 = __uint_as_float(hp1 << 16);
        float h3 = __uint_as_float(hp1 & 0xffff0000u);
        CVT_BF16X2(lp0, wvals[0] - h0, wvals[1] - h1);
        CVT_BF16X2(lp1, wvals[2] - h2, wvals[3] - h3);
        size_t off = (size_t)p * NN * NN + (size_t)(i0 + ti * 4 + a) * NN + j0 + tj * 4;
        *(uint2*)((char*)g_Whi + off * 2) = make_uint2(hp0, hp1);
        *(uint2*)((char*)g_Wlo + off * 2) = make_uint2(lp0, lp1);
    }
}

// ---------------------------------------------------------------------------
__global__ void deg_kernel() {
    int gr = blockIdx.x * 8 + (threadIdx.x >> 5);
    int lane = threadIdx.x & 31;
    const uint32_t* H2 = (const uint32_t*)(g_Whi + (size_t)gr * NN);
    const uint32_t* L2 = (const uint32_t*)(g_Wlo + (size_t)gr * NN);
    float s = 0.f;
    for (int k = lane; k < 512; k += 32) {
        uint32_t h = H2[k], l = L2[k];
        s += __uint_as_float(h << 16) + __uint_as_float(h & 0xffff0000u);
        s += __uint_as_float(l << 16) + __uint_as_float(l & 0xffff0000u);
    }
#pragma unroll
    for (int o = 16; o > 0; o >>= 1) s += __shfl_down_sync(0xffffffffu, s, o);
    if (lane == 0) g_invdeg[gr] = 1.0f / s;
}

// ---------------------------------------------------------------------------
// Tensor-core apply; A and B both staged via cp.async (B pre-split in gmem).
// CTA: 64 rows x 32 cols x K=1024, 128 threads, grid 16 x NP (2 CTAs/SM).
// Epilogue writes fp32 out + split bf16 [n][k] via smem-bounce transpose.
// ---------------------------------------------------------------------------
#define A_SPL   5120                 // 64 rows * 80 B
#define A_TOT   10240                // hi + lo
#define B_SPL   2560                 // 32 n-rows * 80 B
#define B_JOB   5120                 // hi + lo
#define AOFF(b, sp) ((b) * A_TOT + (sp) * A_SPL)
#define BOFF(b, j, NJ) (2 * A_TOT + (b) * ((NJ) * B_JOB) + (j) * B_JOB)
// epilogue bounce (reuses the same smem after mainloop)
#define EP_PITCH 144                 // bytes per n-row (64 k * 2B + 16 pad)
#define EP_OH 0
#define EP_OL 4608
#define EP_AH 9216
#define EP_AL 13824

template <int NJ>
__global__ __launch_bounds__(128) void apply_kernel(int4 j0, int4 j1, int4 j2) {
    extern __shared__ __align__(16) char dsm[];
    uint32_t smb = smem_u32(dsm);

    int tid  = threadIdx.x;
    int lane = tid & 31;
    int wid  = tid >> 5;
    int p    = blockIdx.z;
    int row0 = blockIdx.x * 64;
    int4 jobs[3] = { j0, j1, j2 };

    const float* In[NJ];
    float*       Out[NJ];
    const __nv_bfloat16* FH[NJ];
    const __nv_bfloat16* FL[NJ];
#pragma unroll
    for (int j = 0; j < NJ; j++) {
        In[j]  = &g_feat[jobs[j].x][(size_t)p * NFEAT];
        Out[j] = &g_feat[jobs[j].y][(size_t)p * NFEAT];
        FH[j]  = &g_fH[jobs[j].x][(size_t)p * NFEAT];
        FL[j]  = &g_fL[jobs[j].x][(size_t)p * NFEAT];
    }
    const __nv_bfloat16* WhiP = g_Whi + ((size_t)(p * NN + row0)) * NN;
    const __nv_bfloat16* WloP = g_Wlo + ((size_t)(p * NN + row0)) * NN;

    float acc[NJ][4][4];
#pragma unroll
    for (int j = 0; j < NJ; j++)
#pragma unroll
        for (int n = 0; n < 4; n++)
#pragma unroll
            for (int q = 0; q < 4; q++) acc[j][n][q] = 0.f;

    // A: 64 rows x 32 k bf16 per split; 2 cp16/thread/split
#define STAGE_A(buf, k0)                                                        \
    do {                                                                        \
        _Pragma("unroll")                                                       \
        for (int it = 0; it < 2; it++) {                                        \
            int fi = tid + it * 128;                                            \
            int r  = fi >> 2;                                                   \
            int sg = fi & 3;                                                    \
            cp16(smb + AOFF(buf, 0) + r * 80 + sg * 16,                         \
                 WhiP + (size_t)r * NN + (k0) + sg * 8);                        \
            cp16(smb + AOFF(buf, 1) + r * 80 + sg * 16,                         \
                 WloP + (size_t)r * NN + (k0) + sg * 8);                        \
        }                                                                       \
    } while (0)

    // B: 32 n-rows x 32 k bf16 per split per job; 1 cp16/thread/split/job
#define STAGE_B(buf, k0)                                                        \
    do {                                                                        \
        int n  = tid >> 2;                                                      \
        int sg = tid & 3;                                                       \
        _Pragma("unroll")                                                       \
        for (int j = 0; j < NJ; j++) {                                          \
            cp16(smb + BOFF(buf, j, NJ) + n * 80 + sg * 16,                     \
                 FH[j] + (size_t)n * NN + (k0) + sg * 8);                       \
            cp16(smb + BOFF(buf, j, NJ) + B_SPL + n * 80 + sg * 16,             \
                 FL[j] + (size_t)n * NN + (k0) + sg * 8);                       \
        }                                                                       \
    } while (0)

    // prologue
    STAGE_A(0, 0);
    STAGE_B(0, 0);
    CP_COMMIT();

    for (int c = 0; c < 32; c++) {
        int buf = c & 1;
        CP_WAIT0();
        __syncthreads();

        if (c < 31) {
            STAGE_A(buf ^ 1, (c + 1) * 32);
            STAGE_B(buf ^ 1, (c + 1) * 32);
            CP_COMMIT();
        }

#pragma unroll
        for (int k16 = 0; k16 < 2; k16++) {
            uint32_t ah[4], al[4];
            uint32_t arow = (uint32_t)(wid * 16 + (lane & 15));
            uint32_t aoff = arow * 80 + k16 * 32 + (lane >> 4) * 16;
            ldsm4(ah, smb + AOFF(buf, 0) + aoff);
            ldsm4(al, smb + AOFF(buf, 1) + aoff);
#pragma unroll
            for (int j = 0; j < NJ; j++) {
#pragma unroll
                for (int nt = 0; nt < 4; nt++) {
                    uint32_t boff = (uint32_t)((nt * 8 + (lane & 7)) * 80 +
                                               k16 * 32 + ((lane >> 3) & 1) * 16);
                    uint32_t bh[2], bl[2];
                    ldsm2(bh, smb + BOFF(buf, j, NJ) + boff);
                    ldsm2(bl, smb + BOFF(buf, j, NJ) + B_SPL + boff);
                    mma16816(acc[j][nt], ah, bh);
                    mma16816(acc[j][nt], ah, bl);
                    mma16816(acc[j][nt], al, bh);
                }
            }
        }
        // no trailing store; next iter's CP_WAIT0/sync fences the new buffers
        if (c == 31) __syncthreads();   // protect smem before epilogue bounce
    }

    // epilogue
    int g = lane >> 2, tig = lane & 3;
    int kl0 = wid * 16 + g;            // local k 0..63
    int kl1 = kl0 + 8;
    int r0 = row0 + kl0;
    int r1 = row0 + kl1;
    float idg0 = g_invdeg[p * NN + r0];
    float idg1 = g_invdeg[p * NN + r1];

#pragma unroll
    for (int j = 0; j < NJ; j++) {
        const float* F = In[j];
        float* O = Out[j];
        const float* Dif = (jobs[j].z >= 0) ? &g_feat[jobs[j].z][(size_t)p * NFEAT] : nullptr;
        float*       Abs = (jobs[j].w >= 0) ? &g_feat[jobs[j].w][(size_t)p * NFEAT] : nullptr;

#pragma unroll
        for (int nt = 0; nt < 4; nt++) {
            int col = nt * 8 + 2 * tig;
            float2 v0 = *(const float2*)(F + r0 * DD + col);
            float2 v1 = *(const float2*)(F + r1 * DD + col);
            float2 o0, o1;
            o0.x = 0.5f * fmaf(acc[j][nt][0], idg0, v0.x);
            o0.y = 0.5f * fmaf(acc[j][nt][1], idg0, v0.y);
            o1.x = 0.5f * fmaf(acc[j][nt][2], idg1, v1.x);
            o1.y = 0.5f * fmaf(acc[j][nt][3], idg1, v1.y);
            *(float2*)(O + r0 * DD + col) = o0;
            *(float2*)(O + r1 * DD + col) = o1;

            // split Out into bounce smem [n][k_local]
            __nv_bfloat16 h, l;
            __nv_bfloat16* SH = (__nv_bfloat16*)(dsm + EP_OH);
            __nv_bfloat16* SL = (__nv_bfloat16*)(dsm + EP_OL);
            split_bf16(o0.x, h, l); SH[col * 72 + kl0] = h; SL[col * 72 + kl0] = l;
            split_bf16(o0.y, h, l); SH[(col + 1) * 72 + kl0] = h; SL[(col + 1) * 72 + kl0] = l;
            split_bf16(o1.x, h, l); SH[col * 72 + kl1] = h; SL[col * 72 + kl1] = l;
            split_bf16(o1.y, h, l); SH[(col + 1) * 72 + kl1] = h; SL[(col + 1) * 72 + kl1] = l;

            if (Dif) {
                float2 d0 = *(const float2*)(Dif + r0 * DD + col);
                float2 d1 = *(const float2*)(Dif + r1 * DD + col);
                float2 a0, a1;
                a0.x = fabsf(d0.x - o0.x); a0.y = fabsf(d0.y - o0.y);
                a1.x = fabsf(d1.x - o1.x); a1.y = fabsf(d1.y - o1.y);
                *(float2*)(Abs + r0 * DD + col) = a0;
                *(float2*)(Abs + r1 * DD + col) = a1;
                __nv_bfloat16* TH = (__nv_bfloat16*)(dsm + EP_AH);
                __nv_bfloat16* TL = (__nv_bfloat16*)(dsm + EP_AL);
                split_bf16(a0.x, h, l); TH[col * 72 + kl0] = h; TL[col * 72 + kl0] = l;
                split_bf16(a0.y, h, l); TH[(col + 1) * 72 + kl0] = h; TL[(col + 1) * 72 + kl0] = l;
                split_bf16(a1.x, h, l); TH[col * 72 + kl1] = h; TL[col * 72 + kl1] = l;
                split_bf16(a1.y, h, l); TH[(col + 1) * 72 + kl1] = h; TL[(col + 1) * 72 + kl1] = l;
            }
        }
        __syncthreads();

        // coalesced copy-out of split tiles: [32 n][64 k] bf16 per split
        {
            int n = tid >> 2;
            int q = tid & 3;
            size_t gidx = (size_t)p * NFEAT + (size_t)n * NN + row0 + q * 16;
            __nv_bfloat16* dH = &g_fH[jobs[j].y][gidx];
            __nv_bfloat16* dL = &g_fL[jobs[j].y][gidx];
#pragma unroll
            for (int e = 0; e < 2; e++) {
                *(uint4*)((char*)dH + e * 16) =
                    *(const uint4*)(dsm + EP_OH + n * EP_PITCH + q * 32 + e * 16);
                *(uint4*)((char*)dL + e * 16) =
                    *(const uint4*)(dsm + EP_OL + n * EP_PITCH + q * 32 + e * 16);
            }
            if (jobs[j].w >= 0) {
                __nv_bfloat16* aH = &g_fH[jobs[j].w][gidx];
                __nv_bfloat16* aL = &g_fL[jobs[j].w][gidx];
#pragma unroll
                for (int e = 0; e < 2; e++) {
                    *(uint4*)((char*)aH + e * 16) =
                        *(const uint4*)(dsm + EP_AH + n * EP_PITCH + q * 32 + e * 16);
                    *(uint4*)((char*)aL + e * 16) =
                        *(const uint4*)(dsm + EP_AL + n * EP_PITCH + q * 32 + e * 16);
                }
            }
        }
        __syncthreads();
    }
}

// ---------------------------------------------------------------------------
__global__ void pool_kernel(float* __restrict__ out) {
    __shared__ float red[8][32];
    int blk = blockIdx.x;
    int p   = blockIdx.y;
    int col = threadIdx.x & 31;
    int grp = threadIdx.x >> 5;
    const float* src = &g_feat[c_pool_idx[blk]][(size_t)p * NFEAT];
    float s = 0.f;
    for (int i = 0; i < 128; i++)
        s += src[(grp * 128 + i) * DD + col];
    red[grp][col] = s;
    __syncthreads();
    if (grp == 0) {
        float t = 0.f;
#pragma unroll
        for (int g = 0; g < 8; g++) t += red[g][col];
        int b = p >> 2, w = p & 3;
        out[b * (NW * 224) + w * 224 + blk * 32 + col] = t * (1.0f / 1024.0f);
    }
}

// ---------------------------------------------------------------------------
extern "C" void kernel_launch(void* const* d_in, const int* in_sizes, int n_in,
                              void* d_out, int out_size) {
    const float* pc     = (const float*)d_in[0];
    const float* alphas = (const float*)d_in[1];
    const float* sigma  = (const float*)d_in[2];
    float* out = (float*)d_out;

    const int smem1 = 2 * A_TOT + 2 * 1 * B_JOB;   // 30720
    const int smem2 = 2 * A_TOT + 2 * 2 * B_JOB;   // 40960
    const int smem3 = 2 * A_TOT + 2 * 3 * B_JOB;   // 51200
    cudaFuncSetAttribute(apply_kernel<1>, cudaFuncAttributeMaxDynamicSharedMemorySize, smem1);
    cudaFuncSetAttribute(apply_kernel<2>, cudaFuncAttributeMaxDynamicSharedMemorySize, smem2);
    cudaFuncSetAttribute(apply_kernel<3>, cudaFuncAttributeMaxDynamicSharedMemorySize, smem3);

    build_X_kernel<<<FSZ / 256, 256>>>(pc, alphas);
    build_Xsplit_kernel<<<FSZ / 256, 256>>>(pc, alphas);
    sq_kernel<<<(NP * NN) / 256, 256>>>();
    w_kernel<<<dim3(16, 16, NP), 256>>>(sigma);
    deg_kernel<<<(NP * NN) / 8, 256>>>();

    int4 dummy = make_int4(IX, ITA, -1, -1);
    dim3 grid(16, 1, NP);   // 256 CTAs, 64 rows each -> 2 CTAs/SM
    auto run1 = [&](int4 a) { apply_kernel<1><<<grid, 128, smem1>>>(a, dummy, dummy); };
    auto run2 = [&](int4 a, int4 b) { apply_kernel<2><<<grid, 128, smem2>>>(a, b, dummy); };
    auto run3 = [&](int4 a, int4 b, int4 c) { apply_kernel<3><<<grid, 128, smem3>>>(a, b, c); };
    #define J4(i, o, df, ab) make_int4(i, o, df, ab)

    run1(J4(IX,  IY1, -1, -1));
    run1(J4(IY1, IY2, IY1, IF0));
    run2(J4(IY2, ITA, -1, -1), J4(IF0, IA1, -1, -1));
    run2(J4(ITA, IY4, IY2, IF1), J4(IA1, IA2, -1, -1));
    run3(J4(IY4, ITB, -1, -1), J4(IA2, IA3, -1, -1), J4(IF1, IB1, -1, -1));
    run3(J4(ITB, ITA, -1, -1), J4(IA3, IA4, IA2, IS01), J4(IB1, IB2, -1, -1));
    run3(J4(ITA, ITB, -1, -1), J4(IA4, IA5, -1, -1), J4(IB2, IB3, -1, -1));
    run3(J4(ITB, IY8, IY4, IF2), J4(IA5, IA6, -1, -1), J4(IB3, IB4, -1, -1));
    run2(J4(IA6, IA7, -1, -1), J4(IB4, IB5, -1, -1));
    run2(J4(IA7, IA8, IA4, IS02), J4(IB5, IB6, -1, -1));
    run1(J4(IB6, IB7, -1, -1));
    run1(J4(IB7, IB8, IB4, IS12));

    pool_kernel<<<dim3(7, NP), 256>>>(out);
}

// round 16
// speedup vs baseline: 1.0013x; 1.0009x over previous
#include <cuda_runtime.h>
#include <cuda_bf16.h>
#include <cstdint>

// Problem constants
#define BPC   4
#define NW    4
#define NP    16
#define NN    1024
#define DD    32
#define NFEAT (NN*DD)
#define FSZ   (NP*NFEAT)

// Feature buffer indices
#define IX   0
#define IY1  1
#define IY2  2
#define IY4  3
#define IY8  4
#define ITA  5
#define ITB  6
#define IF0  7
#define IF1  8
#define IF2  9
#define IA1  10
#define IA2  11
#define IA3  12
#define IA4  13
#define IA5  14
#define IA6  15
#define IA7  16
#define IA8  17
#define IB1  18
#define IB2  19
#define IB3  20
#define IB4  21
#define IB5  22
#define IB6  23
#define IB7  24
#define IB8  25
#define IS01 26
#define IS02 27
#define IS12 28
#define NBUF 29

__device__ __nv_bfloat16 g_Whi[(size_t)NP * NN * NN];  // 32 MB
__device__ __nv_bfloat16 g_Wlo[(size_t)NP * NN * NN];  // 32 MB
__device__ float g_feat[NBUF][FSZ];                    // fp32 (epilogue/pool)
// split bf16 features in [n][k] layout: index p*NFEAT + n*NN + k
__device__ __nv_bfloat16 g_fH[NBUF][FSZ];
__device__ __nv_bfloat16 g_fL[NBUF][FSZ];
__device__ float g_sq[NP * NN];
__device__ float g_invdeg[NP * NN];

__constant__ int c_pool_idx[7] = { IX, IF0, IF1, IF2, IS01, IS02, IS12 };

// ---------------------------------------------------------------------------
// helpers
// ---------------------------------------------------------------------------
__device__ __forceinline__ uint32_t smem_u32(const void* p) {
    uint32_t a;
    asm("{ .reg .u64 t; cvta.to.shared.u64 t, %1; cvt.u32.u64 %0, t; }"
        : "=r"(a) : "l"(p));
    return a;
}
#define CVT_BF16X2(res, a, b) \
    asm("cvt.rn.bf16x2.f32 %0, %1, %2;" : "=r"(res) : "f"(b), "f"(a))

__device__ __forceinline__ void cp16(uint32_t s, const void* g) {
    asm volatile("cp.async.cg.shared.global [%0], [%1], 16;" :: "r"(s), "l"(g));
}
#define CP_COMMIT() asm volatile("cp.async.commit_group;" ::: "memory")
#define CP_WAIT0()  asm volatile("cp.async.wait_group 0;" ::: "memory")
#define CP_WAIT1()  asm volatile("cp.async.wait_group 1;" ::: "memory")

__device__ __forceinline__ void ldsm4(uint32_t* r, uint32_t a) {
    asm volatile("ldmatrix.sync.aligned.m8n8.x4.shared.b16 {%0,%1,%2,%3}, [%4];"
                 : "=r"(r[0]), "=r"(r[1]), "=r"(r[2]), "=r"(r[3]) : "r"(a));
}
__device__ __forceinline__ void ldsm2(uint32_t* r, uint32_t a) {
    asm volatile("ldmatrix.sync.aligned.m8n8.x2.shared.b16 {%0,%1}, [%2];"
                 : "=r"(r[0]), "=r"(r[1]) : "r"(a));
}
__device__ __forceinline__ void mma16816(float* d, const uint32_t* a, const uint32_t* b) {
    asm volatile(
        "mma.sync.aligned.m16n8k16.row.col.f32.bf16.bf16.f32 "
        "{%0,%1,%2,%3}, {%4,%5,%6,%7}, {%8,%9}, {%0,%1,%2,%3};"
        : "+f"(d[0]), "+f"(d[1]), "+f"(d[2]), "+f"(d[3])
        : "r"(a[0]), "r"(a[1]), "r"(a[2]), "r"(a[3]), "r"(b[0]), "r"(b[1]));
}

// exp(t) for t in [-0.694, ~0]: degree-6 Taylor, abs err <= 1.6e-5
__device__ __forceinline__ float exp_poly(float t) {
    float p = fmaf(t, 1.0f / 720.0f, 1.0f / 120.0f);
    p = fmaf(t, p, 1.0f / 24.0f);
    p = fmaf(t, p, 1.0f / 6.0f);
    p = fmaf(t, p, 0.5f);
    p = fmaf(t, p, 1.0f);
    p = fmaf(t, p, 1.0f);
    return p;
}

__device__ __forceinline__ void split_bf16(float v, __nv_bfloat16& h, __nv_bfloat16& l) {
    h = __float2bfloat16_rn(v);
    l = __float2bfloat16_rn(v - __bfloat162float(h));
}

// ---------------------------------------------------------------------------
// X fp32 (natural layout) : X[p][n][d] = pc[b][n][d] * alphas[w][d]
// ---------------------------------------------------------------------------
__global__ void build_X_kernel(const float* __restrict__ pc,
                               const float* __restrict__ alphas) {
    int idx = blockIdx.x * blockDim.x + threadIdx.x;
    int d = idx & 31;
    int n = (idx >> 5) & 1023;
    int p = idx >> 15;
    int b = p >> 2;
    int w = p & 3;
    g_feat[IX][idx] = pc[(b * NN + n) * DD + d] * alphas[w * DD + d];
}

// X split bf16 in [d][n] (=[n-of-B][k]) layout
__global__ void build_Xsplit_kernel(const float* __restrict__ pc,
                                    const float* __restrict__ alphas) {
    int idx = blockIdx.x * blockDim.x + threadIdx.x;   // (p, d, n)
    int n = idx & 1023;
    int d = (idx >> 10) & 31;
    int p = idx >> 15;
    int b = p >> 2;
    int w = p & 3;
    float x = pc[(b * NN + n) * DD + d] * alphas[w * DD + d];
    __nv_bfloat16 h, l;
    split_bf16(x, h, l);
    g_fH[IX][p * NFEAT + d * NN + n] = h;
    g_fL[IX][p * NFEAT + d * NN + n] = l;
}

// ---------------------------------------------------------------------------
__global__ void sq_kernel() {
    int gr = blockIdx.x * blockDim.x + threadIdx.x;
    const float4* row = (const float4*)&g_feat[IX][(size_t)gr * DD];
    float s = 0.f;
#pragma unroll
    for (int i = 0; i < 8; i++) {
        float4 v = row[i];
        s += v.x * v.x + v.y * v.y + v.z * v.z + v.w * v.w;
    }
    g_sq[gr] = s;
}

// ---------------------------------------------------------------------------
// W[p][i][j] = K if K >= 0.5 else 0 ; emit bf16 split hi/lo directly.
// ---------------------------------------------------------------------------
__global__ __launch_bounds__(256) void w_kernel(const float* __restrict__ sigma_ptr) {
    __shared__ float Xis[DD][68];
    __shared__ float Xjs[DD][68];

    int p  = blockIdx.z;
    int i0 = blockIdx.y * 64;
    int j0 = blockIdx.x * 64;
    int tid = threadIdx.x;
    float sigma = sigma_ptr[0];
    float invsig = 1.0f / sigma;
    float thr = sigma * 0.69314718055994530942f;

    const float* Xp = &g_feat[IX][(size_t)p * NFEAT];

#pragma unroll
    for (int it = 0; it < 2; it++) {
        int fi = tid + it * 256;
        int r  = fi >> 3;
        int c4 = (fi & 7) << 2;
        float4 vi = *(const float4*)(Xp + (i0 + r) * DD + c4);
        Xis[c4 + 0][r] = vi.x; Xis[c4 + 1][r] = vi.y;
        Xis[c4 + 2][r] = vi.z; Xis[c4 + 3][r] = vi.w;
        float4 vj = *(const float4*)(Xp + (j0 + r) * DD + c4);
        Xjs[c4 + 0][r] = vj.x; Xjs[c4 + 1][r] = vj.y;
        Xjs[c4 + 2][r] = vj.z; Xjs[c4 + 3][r] = vj.w;
    }
    __syncthreads();

    int ti = tid >> 4;
    int tj = tid & 15;
    float acc[4][4];
#pragma unroll
    for (int a = 0; a < 4; a++)
#pragma unroll
        for (int b = 0; b < 4; b++) acc[a][b] = 0.f;

#pragma unroll
    for (int d = 0; d < DD; d++) {
        float4 xa = *(const float4*)&Xis[d][ti * 4];
        float4 xb = *(const float4*)&Xjs[d][tj * 4];
        float ar[4] = { xa.x, xa.y, xa.z, xa.w };
        float br[4] = { xb.x, xb.y, xb.z, xb.w };
#pragma unroll
        for (int a = 0; a < 4; a++)
#pragma unroll
            for (int b = 0; b < 4; b++) acc[a][b] += ar[a] * br[b];
    }

    float sqi[4], sqj[4];
#pragma unroll
    for (int a = 0; a < 4; a++) sqi[a] = g_sq[p * NN + i0 + ti * 4 + a];
#pragma unroll
    for (int b = 0; b < 4; b++) sqj[b] = g_sq[p * NN + j0 + tj * 4 + b];

#pragma unroll
    for (int a = 0; a < 4; a++) {
        float wvals[4];
#pragma unroll
        for (int b = 0; b < 4; b++) {
            float dist = sqi[a] + sqj[b] - 2.f * acc[a][b];
            float K = exp_poly(-dist * invsig);
            wvals[b] = (dist <= thr) ? K : 0.f;
        }
        uint32_t hp0, hp1, lp0, lp1;
        CVT_BF16X2(hp0, wvals[0], wvals[1]);
        CVT_BF16X2(hp1, wvals[2], wvals[3]);
        float h0 = __uint_as_float(hp0 << 16);
        float h1 = __uint_as_float(hp0 & 0xffff0000u);
        float h2 = __uint_as_float(hp1 << 16);
        float h3 = __uint_as_float(hp1 & 0xffff0000u);
        CVT_BF16X2(lp0, wvals[0] - h0, wvals[1] - h1);
        CVT_BF16X2(lp1, wvals[2] - h2, wvals[3] - h3);
        size_t off = (size_t)p * NN * NN + (size_t)(i0 + ti * 4 + a) * NN + j0 + tj * 4;
        *(uint2*)((char*)g_Whi + off * 2) = make_uint2(hp0, hp1);
        *(uint2*)((char*)g_Wlo + off * 2) = make_uint2(lp0, lp1);
    }
}

// ---------------------------------------------------------------------------
__global__ void deg_kernel() {
    int gr = blockIdx.x * 8 + (threadIdx.x >> 5);
    int lane = threadIdx.x & 31;
    const uint32_t* H2 = (const uint32_t*)(g_Whi + (size_t)gr * NN);
    const uint32_t* L2 = (const uint32_t*)(g_Wlo + (size_t)gr * NN);
    float s = 0.f;
    for (int k = lane; k < 512; k += 32) {
        uint32_t h = H2[k], l = L2[k];
        s += __uint_as_float(h << 16) + __uint_as_float(h & 0xffff0000u);
        s += __uint_as_float(l << 16) + __uint_as_float(l & 0xffff0000u);
    }
#pragma unroll
    for (int o = 16; o > 0; o >>= 1) s += __shfl_down_sync(0xffffffffu, s, o);
    if (lane == 0) g_invdeg[gr] = 1.0f / s;
}

// ---------------------------------------------------------------------------
// Tensor-core apply; A and B staged via cp.async, 3-STAGE pipeline
// (prefetch distance 2, cp.async.wait_group 1) to cover DRAM latency.
// CTA: 64 rows x 32 cols x K=1024, 128 threads, grid 16 x NP (2 CTAs/SM).
// ---------------------------------------------------------------------------
#define A_SPL   5120                 // 64 rows * 80 B
#define A_TOT   10240                // hi + lo
#define B_SPL   2560                 // 32 n-rows * 80 B
#define B_JOB   5120                 // hi + lo
#define NSTAGE  3
#define AOFF(b, sp) ((b) * A_TOT + (sp) * A_SPL)
#define BOFF(b, j, NJ) (NSTAGE * A_TOT + (b) * ((NJ) * B_JOB) + (j) * B_JOB)
// epilogue bounce (reuses the same smem after mainloop)
#define EP_PITCH 144                 // bytes per n-row (64 k * 2B + 16 pad)
#define EP_OH 0
#define EP_OL 4608
#define EP_AH 9216
#define EP_AL 13824

template <int NJ>
__global__ __launch_bounds__(128) void apply_kernel(int4 j0, int4 j1, int4 j2) {
    extern __shared__ __align__(16) char dsm[];
    uint32_t smb = smem_u32(dsm);

    int tid  = threadIdx.x;
    int lane = tid & 31;
    int wid  = tid >> 5;
    int p    = blockIdx.z;
    int row0 = blockIdx.x * 64;
    int4 jobs[3] = { j0, j1, j2 };

    const float* In[NJ];
    float*       Out[NJ];
    const __nv_bfloat16* FH[NJ];
    const __nv_bfloat16* FL[NJ];
#pragma unroll
    for (int j = 0; j < NJ; j++) {
        In[j]  = &g_feat[jobs[j].x][(size_t)p * NFEAT];
        Out[j] = &g_feat[jobs[j].y][(size_t)p * NFEAT];
        FH[j]  = &g_fH[jobs[j].x][(size_t)p * NFEAT];
        FL[j]  = &g_fL[jobs[j].x][(size_t)p * NFEAT];
    }
    const __nv_bfloat16* WhiP = g_Whi + ((size_t)(p * NN + row0)) * NN;
    const __nv_bfloat16* WloP = g_Wlo + ((size_t)(p * NN + row0)) * NN;

    float acc[NJ][4][4];
#pragma unroll
    for (int j = 0; j < NJ; j++)
#pragma unroll
        for (int n = 0; n < 4; n++)
#pragma unroll
            for (int q = 0; q < 4; q++) acc[j][n][q] = 0.f;

#define STAGE_A(buf, k0)                                                        \
    do {                                                                        \
        _Pragma("unroll")                                                       \
        for (int it = 0; it < 2; it++) {                                        \
            int fi = tid + it * 128;                                            \
            int r  = fi >> 2;                                                   \
            int sg = fi & 3;                                                    \
            cp16(smb + AOFF(buf, 0) + r * 80 + sg * 16,                         \
                 WhiP + (size_t)r * NN + (k0) + sg * 8);                        \
            cp16(smb + AOFF(buf, 1) + r * 80 + sg * 16,                         \
                 WloP + (size_t)r * NN + (k0) + sg * 8);                        \
        }                                                                       \
    } while (0)

#define STAGE_B(buf, k0)                                                        \
    do {                                                                        \
        int n  = tid >> 2;                                                      \
        int sg = tid & 3;                                                       \
        _Pragma("unroll")                                                       \
        for (int j = 0; j < NJ; j++) {                                          \
            cp16(smb + BOFF(buf, j, NJ) + n * 80 + sg * 16,                     \
                 FH[j] + (size_t)n * NN + (k0) + sg * 8);                       \
            cp16(smb + BOFF(buf, j, NJ) + B_SPL + n * 80 + sg * 16,             \
                 FL[j] + (size_t)n * NN + (k0) + sg * 8);                       \
        }                                                                       \
    } while (0)

    // prologue: stage chunks 0 and 1
    STAGE_A(0, 0);
    STAGE_B(0, 0);
    CP_COMMIT();
    STAGE_A(1, 32);
    STAGE_B(1, 32);
    CP_COMMIT();

    int buf = 0;
    for (int c = 0; c < 32; c++) {
        // wait for chunk c (allow chunk c+1's group to stay in flight)
        if (c == 31) CP_WAIT0(); else CP_WAIT1();
        __syncthreads();   // also guarantees all warps done with buffer (c-1)%3

        if (c + 2 < 32) {
            int nbuf = buf + 2; if (nbuf >= NSTAGE) nbuf -= NSTAGE;
            STAGE_A(nbuf, (c + 2) * 32);
            STAGE_B(nbuf, (c + 2) * 32);
            CP_COMMIT();
        }

#pragma unroll
        for (int k16 = 0; k16 < 2; k16++) {
            uint32_t ah[4], al[4];
            uint32_t arow = (uint32_t)(wid * 16 + (lane & 15));
            uint32_t aoff = arow * 80 + k16 * 32 + (lane >> 4) * 16;
            ldsm4(ah, smb + AOFF(buf, 0) + aoff);
            ldsm4(al, smb + AOFF(buf, 1) + aoff);
#pragma unroll
            for (int j = 0; j < NJ; j++) {
#pragma unroll
                for (int nt = 0; nt < 4; nt++) {
                    uint32_t boff = (uint32_t)((nt * 8 + (lane & 7)) * 80 +
                                               k16 * 32 + ((lane >> 3) & 1) * 16);
                    uint32_t bh[2], bl[2];
                    ldsm2(bh, smb + BOFF(buf, j, NJ) + boff);
                    ldsm2(bl, smb + BOFF(buf, j, NJ) + B_SPL + boff);
                    mma16816(acc[j][nt], ah, bh);
                    mma16816(acc[j][nt], ah, bl);
                    mma16816(acc[j][nt], al, bh);
                }
            }
        }

        if (++buf >= NSTAGE) buf = 0;
    }
    __syncthreads();   // all MMAs done before epilogue reuses smem

    // epilogue
    int g = lane >> 2, tig = lane & 3;
    int kl0 = wid * 16 + g;            // local k 0..63
    int kl1 = kl0 + 8;
    int r0 = row0 + kl0;
    int r1 = row0 + kl1;
    float idg0 = g_invdeg[p * NN + r0];
    float idg1 = g_invdeg[p * NN + r1];

#pragma unroll
    for (int j = 0; j < NJ; j++) {
        const float* F = In[j];
        float* O = Out[j];
        const float* Dif = (jobs[j].z >= 0) ? &g_feat[jobs[j].z][(size_t)p * NFEAT] : nullptr;
        float*       Abs = (jobs[j].w >= 0) ? &g_feat[jobs[j].w][(size_t)p * NFEAT] : nullptr;

#pragma unroll
        for (int nt = 0; nt < 4; nt++) {
            int col = nt * 8 + 2 * tig;
            float2 v0 = *(const float2*)(F + r0 * DD + col);
            float2 v1 = *(const float2*)(F + r1 * DD + col);
            float2 o0, o1;
            o0.x = 0.5f * fmaf(acc[j][nt][0], idg0, v0.x);
            o0.y = 0.5f * fmaf(acc[j][nt][1], idg0, v0.y);
            o1.x = 0.5f * fmaf(acc[j][nt][2], idg1, v1.x);
            o1.y = 0.5f * fmaf(acc[j][nt][3], idg1, v1.y);
            *(float2*)(O + r0 * DD + col) = o0;
            *(float2*)(O + r1 * DD + col) = o1;

            __nv_bfloat16 h, l;
            __nv_bfloat16* SH = (__nv_bfloat16*)(dsm + EP_OH);
            __nv_bfloat16* SL = (__nv_bfloat16*)(dsm + EP_OL);
            split_bf16(o0.x, h, l); SH[col * 72 + kl0] = h; SL[col * 72 + kl0] = l;
            split_bf16(o0.y, h, l); SH[(col + 1) * 72 + kl0] = h; SL[(col + 1) * 72 + kl0] = l;
            split_bf16(o1.x, h, l); SH[col * 72 + kl1] = h; SL[col * 72 + kl1] = l;
            split_bf16(o1.y, h, l); SH[(col + 1) * 72 + kl1] = h; SL[(col + 1) * 72 + kl1] = l;

            if (Dif) {
                float2 d0 = *(const float2*)(Dif + r0 * DD + col);
                float2 d1 = *(const float2*)(Dif + r1 * DD + col);
                float2 a0, a1;
                a0.x = fabsf(d0.x - o0.x); a0.y = fabsf(d0.y - o0.y);
                a1.x = fabsf(d1.x - o1.x); a1.y = fabsf(d1.y - o1.y);
                *(float2*)(Abs + r0 * DD + col) = a0;
                *(float2*)(Abs + r1 * DD + col) = a1;
                __nv_bfloat16* TH = (__nv_bfloat16*)(dsm + EP_AH);
                __nv_bfloat16* TL = (__nv_bfloat16*)(dsm + EP_AL);
                split_bf16(a0.x, h, l); TH[col * 72 + kl0] = h; TL[col * 72 + kl0] = l;
                split_bf16(a0.y, h, l); TH[(col + 1) * 72 + kl0] = h; TL[(col + 1) * 72 + kl0] = l;
                split_bf16(a1.x, h, l); TH[col * 72 + kl1] = h; TL[col * 72 + kl1] = l;
                split_bf16(a1.y, h, l); TH[(col + 1) * 72 + kl1] = h; TL[(col + 1) * 72 + kl1] = l;
            }
        }
        __syncthreads();

        {
            int n = tid >> 2;
            int q = tid & 3;
            size_t gidx = (size_t)p * NFEAT + (size_t)n * NN + row0 + q * 16;
            __nv_bfloat16* dH = &g_fH[jobs[j].y][gidx];
            __nv_bfloat16* dL = &g_fL[jobs[j].y][gidx];
#pragma unroll
            for (int e = 0; e < 2; e++) {
                *(uint4*)((char*)dH + e * 16) =
                    *(const uint4*)(dsm + EP_OH + n * EP_PITCH + q * 32 + e * 16);
                *(uint4*)((char*)dL + e * 16) =
                    *(const uint4*)(dsm + EP_OL + n * EP_PITCH + q * 32 + e * 16);
            }
            if (jobs[j].w >= 0) {
                __nv_bfloat16* aH = &g_fH[jobs[j].w][gidx];
                __nv_bfloat16* aL = &g_fL[jobs[j].w][gidx];
#pragma unroll
                for (int e = 0; e < 2; e++) {
                    *(uint4*)((char*)aH + e * 16) =
                        *(const uint4*)(dsm + EP_AH + n * EP_PITCH + q * 32 + e * 16);
                    *(uint4*)((char*)aL + e * 16) =
                        *(const uint4*)(dsm + EP_AL + n * EP_PITCH + q * 32 + e * 16);
                }
            }
        }
        __syncthreads();
    }
}

// ---------------------------------------------------------------------------
__global__ void pool_kernel(float* __restrict__ out) {
    __shared__ float red[8][32];
    int blk = blockIdx.x;
    int p   = blockIdx.y;
    int col = threadIdx.x & 31;
    int grp = threadIdx.x >> 5;
    const float* src = &g_feat[c_pool_idx[blk]][(size_t)p * NFEAT];
    float s = 0.f;
    for (int i = 0; i < 128; i++)
        s += src[(grp * 128 + i) * DD + col];
    red[grp][col] = s;
    __syncthreads();
    if (grp == 0) {
        float t = 0.f;
#pragma unroll
        for (int g = 0; g < 8; g++) t += red[g][col];
        int b = p >> 2, w = p & 3;
        out[b * (NW * 224) + w * 224 + blk * 32 + col] = t * (1.0f / 1024.0f);
    }
}

// ---------------------------------------------------------------------------
extern "C" void kernel_launch(void* const* d_in, const int* in_sizes, int n_in,
                              void* d_out, int out_size) {
    const float* pc     = (const float*)d_in[0];
    const float* alphas = (const float*)d_in[1];
    const float* sigma  = (const float*)d_in[2];
    float* out = (float*)d_out;

    const int smem1 = NSTAGE * A_TOT + NSTAGE * 1 * B_JOB;   // 46080
    const int smem2 = NSTAGE * A_TOT + NSTAGE * 2 * B_JOB;   // 61440
    const int smem3 = NSTAGE * A_TOT + NSTAGE * 3 * B_JOB;   // 76800
    cudaFuncSetAttribute(apply_kernel<1>, cudaFuncAttributeMaxDynamicSharedMemorySize, smem1);
    cudaFuncSetAttribute(apply_kernel<2>, cudaFuncAttributeMaxDynamicSharedMemorySize, smem2);
    cudaFuncSetAttribute(apply_kernel<3>, cudaFuncAttributeMaxDynamicSharedMemorySize, smem3);

    build_X_kernel<<<FSZ / 256, 256>>>(pc, alphas);
    build_Xsplit_kernel<<<FSZ / 256, 256>>>(pc, alphas);
    sq_kernel<<<(NP * NN) / 256, 256>>>();
    w_kernel<<<dim3(16, 16, NP), 256>>>(sigma);
    deg_kernel<<<(NP * NN) / 8, 256>>>();

    int4 dummy = make_int4(IX, ITA, -1, -1);
    dim3 grid(16, 1, NP);   // 256 CTAs, 64 rows each -> 2 CTAs/SM
    auto run1 = [&](int4 a) { apply_kernel<1><<<grid, 128, smem1>>>(a, dummy, dummy); };
    auto run2 = [&](int4 a, int4 b) { apply_kernel<2><<<grid, 128, smem2>>>(a, b, dummy); };
    auto run3 = [&](int4 a, int4 b, int4 c) { apply_kernel<3><<<grid, 128, smem3>>>(a, b, c); };
    #define J4(i, o, df, ab) make_int4(i, o, df, ab)

    run1(J4(IX,  IY1, -1, -1));
    run1(J4(IY1, IY2, IY1, IF0));
    run2(J4(IY2, ITA, -1, -1), J4(IF0, IA1, -1, -1));
    run2(J4(ITA, IY4, IY2, IF1), J4(IA1, IA2, -1, -1));
    run3(J4(IY4, ITB, -1, -1), J4(IA2, IA3, -1, -1), J4(IF1, IB1, -1, -1));
    run3(J4(ITB, ITA, -1, -1), J4(IA3, IA4, IA2, IS01), J4(IB1, IB2, -1, -1));
    run3(J4(ITA, ITB, -1, -1), J4(IA4, IA5, -1, -1), J4(IB2, IB3, -1, -1));
    run3(J4(ITB, IY8, IY4, IF2), J4(IA5, IA6, -1, -1), J4(IB3, IB4, -1, -1));
    run2(J4(IA6, IA7, -1, -1), J4(IB4, IB5, -1, -1));
    run2(J4(IA7, IA8, IA4, IS02), J4(IB5, IB6, -1, -1));
    run1(J4(IB6, IB7, -1, -1));
    run1(J4(IB7, IB8, IB4, IS12));

    pool_kernel<<<dim3(7, NP), 256>>>(out);
}